// round 1
// baseline (speedup 1.0000x reference)
#include <cuda_runtime.h>
#include <math.h>

#define NROWS 8192
#define DDIM  128
#define INV_T (1.0f/0.07f)

#define TI 64
#define TJ 128
#define NTHREADS 128

// Static device scratch (no allocations allowed).
__device__ float g_fnT[DDIM * NROWS];   // normalized features, k-major: [k][i]
__device__ float g_pos[2 * NROWS];
__device__ float g_neg[2 * NROWS];
__device__ float g_cnt[2 * NROWS];

// ---------------------------------------------------------------------------
// Kernel 1: L2-normalize rows, store transposed (k-major) for tile loads.
// ---------------------------------------------------------------------------
__global__ void norm_kernel(const float* __restrict__ f) {
    int i = blockIdx.x;
    int t = threadIdx.x;              // t == k, 0..127
    float v = f[i * DDIM + t];
    float sq = v * v;
    #pragma unroll
    for (int o = 16; o > 0; o >>= 1)
        sq += __shfl_xor_sync(0xffffffffu, sq, o);
    __shared__ float ws[4];
    if ((t & 31) == 0) ws[t >> 5] = sq;
    __syncthreads();
    float s = ws[0] + ws[1] + ws[2] + ws[3];
    float nrm = fmaxf(sqrtf(s), 1e-8f);
    g_fnT[t * NROWS + i] = v / nrm;
}

// ---------------------------------------------------------------------------
// Packed f32x2 helpers (Blackwell FFMA2, PTX-only pattern).
// ---------------------------------------------------------------------------
__device__ __forceinline__ void fma2(double& c, double a, double b) {
    asm("fma.rn.f32x2 %0, %1, %2, %0;" : "+d"(c) : "d"(a), "d"(b));
}
__device__ __forceinline__ double rep2(float b) {
    double r;
    asm("mov.b64 %0, {%1, %1};" : "=d"(r) : "f"(b));
    return r;
}

// ---------------------------------------------------------------------------
// Kernel 2: fused  sim -> exp -> mask -> row partial sums.
// Block: 128 threads (16 tx x 8 ty). C tile 64 rows x 128 cols per j-step.
// Each thread: 8 rows (as 4 f32x2 row-pairs) x 8 cols.
// blockIdx.x -> i-tile (64 rows), blockIdx.y -> j half (4096 cols).
// ---------------------------------------------------------------------------
extern __shared__ float smem[];

__global__ __launch_bounds__(NTHREADS) void main_kernel(
    const int* __restrict__ pmask, const int* __restrict__ nmask) {
    float* sA = smem;              // [k][i] : 128 x 64  = 32 KB
    float* sB = smem + TI * DDIM;  // [k][j] : 128 x 128 = 64 KB

    const int tid = threadIdx.x;
    const int tx = tid & 15;       // col group
    const int ty = tid >> 4;       // row group
    const int i0 = blockIdx.x * TI;
    const int half = blockIdx.y;
    const int jbase = half * (NROWS / 2);

    // Load A tile once (reused across all j tiles). Coalesced float4 rows.
    #pragma unroll
    for (int p = 0; p < 16; p++) {
        int k = p * 8 + (tid >> 4);
        *(float4*)&sA[k * TI + tx * 4] =
            *(const float4*)&g_fnT[(size_t)k * NROWS + i0 + tx * 4];
    }

    float posA[8], negA[8], cntA[8];
    #pragma unroll
    for (int r = 0; r < 8; r++) { posA[r] = 0.f; negA[r] = 0.f; cntA[r] = 0.f; }

    for (int jt = 0; jt < (NROWS / 2) / TJ; jt++) {
        const int j0 = jbase + jt * TJ;
        __syncthreads();
        // Load B tile (128x128 f32), coalesced.
        #pragma unroll
        for (int p = 0; p < 32; p++) {
            int k = p * 4 + (tid >> 5);
            *(float4*)&sB[k * TJ + (tid & 31) * 4] =
                *(const float4*)&g_fnT[(size_t)k * NROWS + j0 + (tid & 31) * 4];
        }
        __syncthreads();

        // --- GEMM micro-kernel: C[4 row-pairs][8 cols] in packed f32x2 ---
        double C[4][8];
        #pragma unroll
        for (int p = 0; p < 4; p++)
            #pragma unroll
            for (int c = 0; c < 8; c++) C[p][c] = 0.0;

        #pragma unroll 8
        for (int k = 0; k < DDIM; k++) {
            const double* pa = (const double*)&sA[k * TI + ty * 8];
            double a0 = pa[0], a1 = pa[1], a2 = pa[2], a3 = pa[3];
            float4 b0 = *(const float4*)&sB[k * TJ + tx * 8];
            float4 b1 = *(const float4*)&sB[k * TJ + tx * 8 + 4];
            double br[8];
            br[0] = rep2(b0.x); br[1] = rep2(b0.y);
            br[2] = rep2(b0.z); br[3] = rep2(b0.w);
            br[4] = rep2(b1.x); br[5] = rep2(b1.y);
            br[6] = rep2(b1.z); br[7] = rep2(b1.w);
            #pragma unroll
            for (int c = 0; c < 8; c++) {
                fma2(C[0][c], a0, br[c]);
                fma2(C[1][c], a1, br[c]);
                fma2(C[2][c], a2, br[c]);
                fma2(C[3][c], a3, br[c]);
            }
        }

        // --- Fused epilogue: exp, mask, row accumulate ---
        const int jg0 = j0 + tx * 8;
        #pragma unroll
        for (int p = 0; p < 4; p++) {
            #pragma unroll
            for (int h = 0; h < 2; h++) {
                const int rr = p * 2 + h;
                const int ig = i0 + ty * 8 + rr;
                const int4* pm = (const int4*)(pmask + (size_t)ig * NROWS + jg0);
                const int4* nm = (const int4*)(nmask + (size_t)ig * NROWS + jg0);
                int4 pv0 = pm[0], pv1 = pm[1];
                int4 nv0 = nm[0], nv1 = nm[1];
                int pi[8] = {pv0.x, pv0.y, pv0.z, pv0.w, pv1.x, pv1.y, pv1.z, pv1.w};
                int ni[8] = {nv0.x, nv0.y, nv0.z, nv0.w, nv1.x, nv1.y, nv1.z, nv1.w};
                float pos = 0.f, neg = 0.f, cnt = 0.f;
                #pragma unroll
                for (int c = 0; c < 8; c++) {
                    int bits = h ? __double2hiint(C[p][c]) : __double2loint(C[p][c]);
                    float sim = __int_as_float(bits);
                    float e = __expf(sim * INV_T);
                    bool self = (jg0 + c == ig);
                    float pf = (pi[c] != 0 && !self) ? 1.f : 0.f;
                    float nf = (ni[c] != 0 && !self) ? 1.f : 0.f;
                    pos = fmaf(e, pf, pos);
                    neg = fmaf(e, nf, neg);
                    cnt += pf;
                }
                posA[rr] += pos; negA[rr] += neg; cntA[rr] += cnt;
            }
        }
    }

    // Reduce each row across the 16 tx lanes (width-16 xor shuffles).
    #pragma unroll
    for (int r = 0; r < 8; r++) {
        float ps = posA[r], ns = negA[r], cs = cntA[r];
        #pragma unroll
        for (int o = 8; o > 0; o >>= 1) {
            ps += __shfl_xor_sync(0xffffffffu, ps, o, 16);
            ns += __shfl_xor_sync(0xffffffffu, ns, o, 16);
            cs += __shfl_xor_sync(0xffffffffu, cs, o, 16);
        }
        if (tx == 0) {
            int row = i0 + ty * 8 + r;
            g_pos[half * NROWS + row] = ps;
            g_neg[half * NROWS + row] = ns;
            g_cnt[half * NROWS + row] = cs;
        }
    }
}

// ---------------------------------------------------------------------------
// Kernel 3: combine halves, per-row log prob, deterministic mean.
// ---------------------------------------------------------------------------
__global__ void final_kernel(float* __restrict__ out) {
    __shared__ float red[1024];
    int t = threadIdx.x;
    float acc = 0.f;
    for (int r = t; r < NROWS; r += 1024) {
        float pos = g_pos[r] + g_pos[NROWS + r];
        float neg = g_neg[r] + g_neg[NROWS + r];
        float cnt = g_cnt[r] + g_cnt[NROWS + r];
        acc += logf(pos / (pos + neg)) / cnt;
    }
    red[t] = acc;
    __syncthreads();
    for (int s = 512; s > 0; s >>= 1) {
        if (t < s) red[t] += red[t + s];
        __syncthreads();
    }
    if (t == 0) out[0] = -red[0] / (float)NROWS;
}

// ---------------------------------------------------------------------------
extern "C" void kernel_launch(void* const* d_in, const int* in_sizes, int n_in,
                              void* d_out, int out_size) {
    const float* features = (const float*)d_in[0];
    const int*   pmask    = (const int*)d_in[1];
    const int*   nmask    = (const int*)d_in[2];
    float* out = (float*)d_out;

    const int smem_bytes = (TI * DDIM + TJ * DDIM) * sizeof(float);  // 96 KB
    cudaFuncSetAttribute(main_kernel,
                         cudaFuncAttributeMaxDynamicSharedMemorySize, smem_bytes);

    norm_kernel<<<NROWS, DDIM>>>(features);
    dim3 grid(NROWS / TI, 2);
    main_kernel<<<grid, NTHREADS, smem_bytes>>>(pmask, nmask);
    final_kernel<<<1, 1024>>>(out);
}

// round 3
// speedup vs baseline: 2.2781x; 2.2781x over previous
#include <cuda_runtime.h>
#include <cuda_fp16.h>
#include <cstdint>
#include <math.h>

#define NR 8192
#define DDIM 128
#define INV_T (1.0f/0.07f)
#define JSPLIT 2
#define JRANGE (NR/JSPLIT)      /* 4096 */
#define TJ 128
#define NSTEP (JRANGE/TJ)       /* 32 */
#define NT 512

#define SM_AHI 0
#define SM_ALO 32768
#define SM_B0  65536
#define SM_B1  98304
#define SMEM_TOTAL 131072

// Static device scratch (no allocations allowed).
__device__ __half g_hi[(size_t)NR * DDIM];
__device__ __half g_lo[(size_t)NR * DDIM];
__device__ float g_pos[8 * NR];
__device__ float g_neg[8 * NR];
__device__ float g_cnt[8 * NR];

// ---------------------------------------------------------------------------
__device__ __forceinline__ uint32_t smem_u32(const void* p) {
    uint32_t a;
    asm("{ .reg .u64 t; cvta.to.shared.u64 t, %1; cvt.u32.u64 %0, t; }"
        : "=r"(a) : "l"(p));
    return a;
}
__device__ __forceinline__ void cp16(uint32_t dst, const void* src) {
    asm volatile("cp.async.cg.shared.global [%0], [%1], 16;"
                 :: "r"(dst), "l"(src));
}
#define CP_COMMIT() asm volatile("cp.async.commit_group;" ::: "memory")
#define CP_WAIT0()  asm volatile("cp.async.wait_group 0;" ::: "memory")

__device__ __forceinline__ void ldmx4(uint32_t addr, uint32_t& r0, uint32_t& r1,
                                      uint32_t& r2, uint32_t& r3) {
    asm volatile("ldmatrix.sync.aligned.m8n8.x4.shared.b16 {%0,%1,%2,%3}, [%4];"
                 : "=r"(r0), "=r"(r1), "=r"(r2), "=r"(r3) : "r"(addr));
}
__device__ __forceinline__ void mma16816(float* c, const uint32_t* a,
                                         uint32_t b0, uint32_t b1) {
    asm volatile(
        "mma.sync.aligned.m16n8k16.row.col.f32.f16.f16.f32 "
        "{%0,%1,%2,%3},{%4,%5,%6,%7},{%8,%9},{%0,%1,%2,%3};"
        : "+f"(c[0]), "+f"(c[1]), "+f"(c[2]), "+f"(c[3])
        : "r"(a[0]), "r"(a[1]), "r"(a[2]), "r"(a[3]), "r"(b0), "r"(b1));
}
// swizzled byte offset within a 128-row x 256B tile
__device__ __forceinline__ uint32_t swz(int row, int c) {
    return (uint32_t)(row * 256 + ((c ^ (row & 7)) << 4));
}

// ---------------------------------------------------------------------------
// Kernel 1: normalize rows, split fp32 -> fp16 hi + fp16 lo.
// ---------------------------------------------------------------------------
__global__ void prepack_kernel(const float* __restrict__ f) {
    int i = blockIdx.x;
    int t = threadIdx.x;
    float v = f[i * DDIM + t];
    float sq = v * v;
    #pragma unroll
    for (int o = 16; o > 0; o >>= 1) sq += __shfl_xor_sync(0xffffffffu, sq, o);
    __shared__ float ws[4];
    if ((t & 31) == 0) ws[t >> 5] = sq;
    __syncthreads();
    float s = ws[0] + ws[1] + ws[2] + ws[3];
    float fn = v / fmaxf(sqrtf(s), 1e-8f);
    __half hi = __float2half(fn);
    __half lo = __float2half(fn - __half2float(hi));
    g_hi[(size_t)i * DDIM + t] = hi;
    g_lo[(size_t)i * DDIM + t] = lo;
}

// ---------------------------------------------------------------------------
// cp.async fill of one 128x128 fp16 tile (rows k-contiguous, swizzled).
// ---------------------------------------------------------------------------
__device__ __forceinline__ void fill_tile(uint32_t sdst, const __half* gsrc) {
    int tid = threadIdx.x;
    #pragma unroll
    for (int r = 0; r < 4; r++) {
        int idx = tid + r * NT;        // 0..2047
        int row = idx >> 4, c = idx & 15;
        cp16(sdst + swz(row, c),
             (const char*)(gsrc + (size_t)row * DDIM) + c * 16);
    }
}

// ---------------------------------------------------------------------------
// Kernel 2: HMMA GEMM (A=hi+lo vs B=hi) + fused exp/mask/row-sum epilogue.
// Grid (64 i-tiles, JSPLIT). 512 threads, warp grid 4x4, warp tile 32x32.
// ---------------------------------------------------------------------------
extern __shared__ char dsm[];

__global__ __launch_bounds__(NT, 1) void hmma_main(
    const int* __restrict__ pmask, const int* __restrict__ nmask) {
    const uint32_t sb = smem_u32(dsm);
    const int tid = threadIdx.x, lid = tid & 31, wid = tid >> 5;
    const int wm = wid >> 2, wn = wid & 3;
    const int i0 = blockIdx.x * 128;
    const int split = blockIdx.y;
    const int jbase = split * JRANGE;

    fill_tile(sb + SM_AHI, g_hi + (size_t)i0 * DDIM);
    fill_tile(sb + SM_ALO, g_lo + (size_t)i0 * DDIM);
    fill_tile(sb + SM_B0,  g_hi + (size_t)jbase * DDIM);
    CP_COMMIT();
    CP_WAIT0();
    __syncthreads();

    float pos[4] = {0, 0, 0, 0}, neg[4] = {0, 0, 0, 0}, cnt[4] = {0, 0, 0, 0};

    const int arow0 = wm * 32 + (lid & 15);
    const int asel  = lid >> 4;                      // 0/1 -> k chunk parity
    const int brow0 = wn * 32 + (lid & 7) + ((lid & 16) ? 8 : 0);
    const int bsel  = (lid >> 3) & 1;

    for (int t = 0; t < NSTEP; t++) {
        const int buf = t & 1;
        const uint32_t Bbase = sb + (buf ? SM_B1 : SM_B0);
        if (t + 1 < NSTEP) {
            fill_tile(sb + (buf ? SM_B0 : SM_B1),
                      g_hi + (size_t)(jbase + (t + 1) * TJ) * DDIM);
            CP_COMMIT();
        }

        float acc[2][4][4];
        #pragma unroll
        for (int mt = 0; mt < 2; mt++)
            #pragma unroll
            for (int nt = 0; nt < 4; nt++)
                #pragma unroll
                for (int q = 0; q < 4; q++) acc[mt][nt][q] = 0.f;

        #pragma unroll
        for (int pass = 0; pass < 2; pass++) {
            const uint32_t Abase = sb + (pass ? SM_ALO : SM_AHI);
            #pragma unroll
            for (int kk = 0; kk < 8; kk++) {
                uint32_t a[2][4];
                #pragma unroll
                for (int mt = 0; mt < 2; mt++) {
                    int row = arow0 + mt * 16;
                    ldmx4(Abase + swz(row, 2 * kk + asel),
                          a[mt][0], a[mt][1], a[mt][2], a[mt][3]);
                }
                #pragma unroll
                for (int np = 0; np < 2; np++) {
                    int row = brow0 + np * 16;
                    uint32_t b0, b1, b2, b3;
                    ldmx4(Bbase + swz(row, 2 * kk + bsel), b0, b1, b2, b3);
                    #pragma unroll
                    for (int mt = 0; mt < 2; mt++) {
                        mma16816(acc[mt][2 * np],     a[mt], b0, b1);
                        mma16816(acc[mt][2 * np + 1], a[mt], b2, b3);
                    }
                }
            }
        }

        // --- fused epilogue: exp, masks, per-row accumulate ---
        const int j00 = jbase + t * TJ + wn * 32 + (lid & 3) * 2;
        #pragma unroll
        for (int mt = 0; mt < 2; mt++) {
            #pragma unroll
            for (int hf = 0; hf < 2; hf++) {
                const int rr = mt * 2 + hf;
                const int ig = i0 + wm * 32 + mt * 16 + hf * 8 + (lid >> 2);
                const int* pm = pmask + (size_t)ig * NR;
                const int* nm = nmask + (size_t)ig * NR;
                float p = 0.f, n = 0.f, c = 0.f;
                #pragma unroll
                for (int nt = 0; nt < 4; nt++) {
                    const int j = j00 + nt * 8;
                    int2 pv = *(const int2*)(pm + j);
                    int2 nv = *(const int2*)(nm + j);
                    float e0 = __expf(acc[mt][nt][hf * 2 + 0] * INV_T);
                    float e1 = __expf(acc[mt][nt][hf * 2 + 1] * INV_T);
                    bool s0 = (j == ig), s1 = (j + 1 == ig);
                    float pf0 = (pv.x != 0 && !s0) ? 1.f : 0.f;
                    float pf1 = (pv.y != 0 && !s1) ? 1.f : 0.f;
                    float nf0 = (nv.x != 0 && !s0) ? 1.f : 0.f;
                    float nf1 = (nv.y != 0 && !s1) ? 1.f : 0.f;
                    p = fmaf(e0, pf0, p); p = fmaf(e1, pf1, p);
                    n = fmaf(e0, nf0, n); n = fmaf(e1, nf1, n);
                    c += pf0 + pf1;
                }
                pos[rr] += p; neg[rr] += n; cnt[rr] += c;
            }
        }

        if (t + 1 < NSTEP) CP_WAIT0();
        __syncthreads();
    }

    // quad-lane reduce (lanes sharing a row differ only in lid&3) + store
    #pragma unroll
    for (int rr = 0; rr < 4; rr++) {
        float p = pos[rr], n = neg[rr], c = cnt[rr];
        p += __shfl_xor_sync(0xffffffffu, p, 1);
        p += __shfl_xor_sync(0xffffffffu, p, 2);
        n += __shfl_xor_sync(0xffffffffu, n, 1);
        n += __shfl_xor_sync(0xffffffffu, n, 2);
        c += __shfl_xor_sync(0xffffffffu, c, 1);
        c += __shfl_xor_sync(0xffffffffu, c, 2);
        if ((lid & 3) == 0) {
            int mt = rr >> 1, hf = rr & 1;
            int ig = i0 + wm * 32 + mt * 16 + hf * 8 + (lid >> 2);
            int part = split * 4 + wn;
            g_pos[part * NR + ig] = p;
            g_neg[part * NR + ig] = n;
            g_cnt[part * NR + ig] = c;
        }
    }
}

// ---------------------------------------------------------------------------
// Kernel 3: combine 8 partials, per-row log prob, deterministic mean.
// ---------------------------------------------------------------------------
__global__ void final_kernel(float* __restrict__ out) {
    __shared__ float red[1024];
    int t = threadIdx.x;
    float acc = 0.f;
    for (int r = t; r < NR; r += 1024) {
        float pos = 0.f, neg = 0.f, cnt = 0.f;
        #pragma unroll
        for (int p = 0; p < 8; p++) {
            pos += g_pos[p * NR + r];
            neg += g_neg[p * NR + r];
            cnt += g_cnt[p * NR + r];
        }
        acc += logf(pos / (pos + neg)) / cnt;
    }
    red[t] = acc;
    __syncthreads();
    for (int s = 512; s > 0; s >>= 1) {
        if (t < s) red[t] += red[t + s];
        __syncthreads();
    }
    if (t == 0) out[0] = -red[0] / (float)NR;
}

// ---------------------------------------------------------------------------
extern "C" void kernel_launch(void* const* d_in, const int* in_sizes, int n_in,
                              void* d_out, int out_size) {
    const float* features = (const float*)d_in[0];
    const int*   pmask    = (const int*)d_in[1];
    const int*   nmask    = (const int*)d_in[2];
    float* out = (float*)d_out;

    cudaFuncSetAttribute(hmma_main,
                         cudaFuncAttributeMaxDynamicSharedMemorySize, SMEM_TOTAL);

    prepack_kernel<<<NR, DDIM>>>(features);
    dim3 grid(NR / 128, JSPLIT);
    hmma_main<<<grid, NT, SMEM_TOTAL>>>(pmask, nmask);
    final_kernel<<<1, 1024>>>(out);
}

// round 4
// speedup vs baseline: 2.9601x; 1.2994x over previous
#include <cuda_runtime.h>
#include <cuda_fp16.h>
#include <cstdint>
#include <math.h>

#define NR 8192
#define DDIM 128
#define EXPK ((1.0f/0.07f)*1.44269504f)   /* INV_T * log2(e) */
#define JSPLIT 2
#define JRANGE (NR/JSPLIT)      /* 4096 */
#define TI 64
#define TJ 128
#define NSTEP (JRANGE/TJ)       /* 32 */
#define NT 256

#define SM_AHI 0
#define SM_ALO 16384
#define SM_B0  32768
#define SM_B1  65536
#define SMEM_TOTAL 98304        /* 96 KB -> 2 CTAs/SM */

// Static device scratch (no allocations allowed).
__device__ __half g_hi[(size_t)NR * DDIM];
__device__ __half g_lo[(size_t)NR * DDIM];
__device__ float g_pos[8 * NR];
__device__ float g_neg[8 * NR];
__device__ float g_cnt[8 * NR];

// ---------------------------------------------------------------------------
__device__ __forceinline__ uint32_t smem_u32(const void* p) {
    uint32_t a;
    asm("{ .reg .u64 t; cvta.to.shared.u64 t, %1; cvt.u32.u64 %0, t; }"
        : "=r"(a) : "l"(p));
    return a;
}
__device__ __forceinline__ void cp16(uint32_t dst, const void* src) {
    asm volatile("cp.async.cg.shared.global [%0], [%1], 16;"
                 :: "r"(dst), "l"(src));
}
#define CP_COMMIT() asm volatile("cp.async.commit_group;" ::: "memory")
#define CP_WAIT0()  asm volatile("cp.async.wait_group 0;" ::: "memory")

__device__ __forceinline__ void ldmx4(uint32_t addr, uint32_t& r0, uint32_t& r1,
                                      uint32_t& r2, uint32_t& r3) {
    asm volatile("ldmatrix.sync.aligned.m8n8.x4.shared.b16 {%0,%1,%2,%3}, [%4];"
                 : "=r"(r0), "=r"(r1), "=r"(r2), "=r"(r3) : "r"(addr));
}
__device__ __forceinline__ void mma16816(float* c, const uint32_t* a,
                                         uint32_t b0, uint32_t b1) {
    asm volatile(
        "mma.sync.aligned.m16n8k16.row.col.f32.f16.f16.f32 "
        "{%0,%1,%2,%3},{%4,%5,%6,%7},{%8,%9},{%0,%1,%2,%3};"
        : "+f"(c[0]), "+f"(c[1]), "+f"(c[2]), "+f"(c[3])
        : "r"(a[0]), "r"(a[1]), "r"(a[2]), "r"(a[3]), "r"(b0), "r"(b1));
}
// swizzled byte offset within a tile of 256B rows
__device__ __forceinline__ uint32_t swz(int row, int c) {
    return (uint32_t)(row * 256 + ((c ^ (row & 7)) << 4));
}
__device__ __forceinline__ float mask2f(int m) {
    return __int_as_float(m * 0x3f800000);   // m in {0,1}
}

// ---------------------------------------------------------------------------
// Kernel 1: normalize rows, split fp32 -> fp16 hi + fp16 lo. Warp per row.
// ---------------------------------------------------------------------------
__global__ void prepack_kernel(const float* __restrict__ f) {
    int row = blockIdx.x * 8 + (threadIdx.x >> 5);
    int l = threadIdx.x & 31;
    float4 v = *(const float4*)(f + (size_t)row * DDIM + l * 4);
    float sq = fmaf(v.x, v.x, fmaf(v.y, v.y, fmaf(v.z, v.z, v.w * v.w)));
    #pragma unroll
    for (int o = 16; o > 0; o >>= 1) sq += __shfl_xor_sync(0xffffffffu, sq, o);
    float inv = 1.0f / fmaxf(sqrtf(sq), 1e-8f);
    float fn[4] = {v.x * inv, v.y * inv, v.z * inv, v.w * inv};
    uint2 uh, ul;
    {
        __half h0 = __float2half(fn[0]), h1 = __float2half(fn[1]);
        __half h2 = __float2half(fn[2]), h3 = __float2half(fn[3]);
        __half l0 = __float2half(fn[0] - __half2float(h0));
        __half l1 = __float2half(fn[1] - __half2float(h1));
        __half l2 = __float2half(fn[2] - __half2float(h2));
        __half l3 = __float2half(fn[3] - __half2float(h3));
        __half2 a = __halves2half2(h0, h1), b = __halves2half2(h2, h3);
        __half2 c = __halves2half2(l0, l1), d = __halves2half2(l2, l3);
        uh.x = *(uint32_t*)&a; uh.y = *(uint32_t*)&b;
        ul.x = *(uint32_t*)&c; ul.y = *(uint32_t*)&d;
    }
    *(uint2*)(g_hi + (size_t)row * DDIM + l * 4) = uh;
    *(uint2*)(g_lo + (size_t)row * DDIM + l * 4) = ul;
}

// ---------------------------------------------------------------------------
template<int ROWS>
__device__ __forceinline__ void fill_tile(uint32_t sdst, const __half* gsrc, int tid) {
    #pragma unroll
    for (int r = 0; r < ROWS * 16 / NT; r++) {
        int idx = tid + r * NT;
        int row = idx >> 4, c = idx & 15;
        cp16(sdst + swz(row, c),
             (const char*)(gsrc + (size_t)row * DDIM) + c * 16);
    }
}

// ---------------------------------------------------------------------------
// Kernel 2: HMMA GEMM (A=hi+lo vs B=hi) + fused exp/mask/row-sum epilogue.
// Grid (128 i-tiles, 2 j-splits). 256 threads, warps 2x4, warp tile 32x32.
// ---------------------------------------------------------------------------
extern __shared__ char dsm[];

__global__ __launch_bounds__(NT, 2) void hmma_main(
    const int* __restrict__ pmask, const int* __restrict__ nmask) {
    const uint32_t sb = smem_u32(dsm);
    const int tid = threadIdx.x, lid = tid & 31, wid = tid >> 5;
    const int wm = wid >> 2, wn = wid & 3;
    const int i0 = blockIdx.x * TI;
    const int split = blockIdx.y;
    const int jbase = split * JRANGE;

    fill_tile<TI>(sb + SM_AHI, g_hi + (size_t)i0 * DDIM, tid);
    fill_tile<TI>(sb + SM_ALO, g_lo + (size_t)i0 * DDIM, tid);
    fill_tile<TJ>(sb + SM_B0,  g_hi + (size_t)jbase * DDIM, tid);
    CP_COMMIT();
    CP_WAIT0();
    __syncthreads();

    float pos[4] = {0, 0, 0, 0}, neg[4] = {0, 0, 0, 0};
    int cnt[4] = {0, 0, 0, 0};

    const int arow0 = wm * 32 + (lid & 15);
    const int asel  = lid >> 4;
    const int brow0 = wn * 32 + (lid & 7) + ((lid & 16) ? 8 : 0);
    const int bsel  = (lid >> 3) & 1;
    const int idiag = (i0 & ~127);   // 128-aligned block containing this i-tile

    for (int t = 0; t < NSTEP; t++) {
        const int buf = t & 1;
        const uint32_t Bbase = sb + (buf ? SM_B1 : SM_B0);
        const int j0 = jbase + t * TJ;
        if (t + 1 < NSTEP) {
            fill_tile<TJ>(sb + (buf ? SM_B0 : SM_B1),
                          g_hi + (size_t)(j0 + TJ) * DDIM, tid);
            CP_COMMIT();
        }
        // L2-prefetch this step's mask block (64 rows x 512B, both masks)
        {
            const char* pp = (const char*)(pmask + (size_t)(i0 + (tid >> 2)) * NR + j0)
                             + (tid & 3) * 128;
            const char* np = (const char*)(nmask + (size_t)(i0 + (tid >> 2)) * NR + j0)
                             + (tid & 3) * 128;
            asm volatile("prefetch.global.L2 [%0];" :: "l"(pp));
            asm volatile("prefetch.global.L2 [%0];" :: "l"(np));
        }

        float acc[2][4][4];
        #pragma unroll
        for (int mt = 0; mt < 2; mt++)
            #pragma unroll
            for (int nt = 0; nt < 4; nt++)
                #pragma unroll
                for (int q = 0; q < 4; q++) acc[mt][nt][q] = 0.f;

        #pragma unroll
        for (int kk = 0; kk < 8; kk++) {
            uint32_t b[2][4];
            #pragma unroll
            for (int np = 0; np < 2; np++)
                ldmx4(Bbase + swz(brow0 + np * 16, 2 * kk + bsel),
                      b[np][0], b[np][1], b[np][2], b[np][3]);
            #pragma unroll
            for (int pass = 0; pass < 2; pass++) {
                const uint32_t Abase = sb + (pass ? SM_ALO : SM_AHI);
                uint32_t a[2][4];
                #pragma unroll
                for (int mt = 0; mt < 2; mt++)
                    ldmx4(Abase + swz(arow0 + mt * 16, 2 * kk + asel),
                          a[mt][0], a[mt][1], a[mt][2], a[mt][3]);
                #pragma unroll
                for (int np = 0; np < 2; np++)
                    #pragma unroll
                    for (int mt = 0; mt < 2; mt++) {
                        mma16816(acc[mt][2 * np],     a[mt], b[np][0], b[np][1]);
                        mma16816(acc[mt][2 * np + 1], a[mt], b[np][2], b[np][3]);
                    }
            }
        }

        // --- fused epilogue ---
        const bool diag = (j0 == idiag);
        const int j00 = j0 + wn * 32 + (lid & 3) * 2;
        #pragma unroll
        for (int mt = 0; mt < 2; mt++) {
            #pragma unroll
            for (int hf = 0; hf < 2; hf++) {
                const int rr = mt * 2 + hf;
                const int ig = i0 + wm * 32 + mt * 16 + hf * 8 + (lid >> 2);
                const int* pm = pmask + (size_t)ig * NR;
                const int* nm = nmask + (size_t)ig * NR;
                float p = pos[rr], n = neg[rr];
                int c = cnt[rr];
                #pragma unroll
                for (int nt = 0; nt < 4; nt++) {
                    const int j = j00 + nt * 8;
                    int2 pv = *(const int2*)(pm + j);
                    int2 nv = *(const int2*)(nm + j);
                    if (diag) {
                        if (j == ig)     { pv.x = 0; nv.x = 0; }
                        if (j + 1 == ig) { pv.y = 0; nv.y = 0; }
                    }
                    float e0 = exp2f(acc[mt][nt][hf * 2 + 0] * EXPK);
                    float e1 = exp2f(acc[mt][nt][hf * 2 + 1] * EXPK);
                    p = fmaf(e0, mask2f(pv.x), p);
                    p = fmaf(e1, mask2f(pv.y), p);
                    n = fmaf(e0, mask2f(nv.x), n);
                    n = fmaf(e1, mask2f(nv.y), n);
                    c += pv.x + pv.y;
                }
                pos[rr] = p; neg[rr] = n; cnt[rr] = c;
            }
        }

        if (t + 1 < NSTEP) CP_WAIT0();
        __syncthreads();
    }

    // quad-lane reduce (lanes sharing a row differ only in lid&3) + store
    #pragma unroll
    for (int rr = 0; rr < 4; rr++) {
        float p = pos[rr], n = neg[rr], c = (float)cnt[rr];
        p += __shfl_xor_sync(0xffffffffu, p, 1);
        p += __shfl_xor_sync(0xffffffffu, p, 2);
        n += __shfl_xor_sync(0xffffffffu, n, 1);
        n += __shfl_xor_sync(0xffffffffu, n, 2);
        c += __shfl_xor_sync(0xffffffffu, c, 1);
        c += __shfl_xor_sync(0xffffffffu, c, 2);
        if ((lid & 3) == 0) {
            int mt = rr >> 1, hf = rr & 1;
            int ig = i0 + wm * 32 + mt * 16 + hf * 8 + (lid >> 2);
            int part = split * 4 + wn;
            g_pos[part * NR + ig] = p;
            g_neg[part * NR + ig] = n;
            g_cnt[part * NR + ig] = c;
        }
    }
}

// ---------------------------------------------------------------------------
// Kernel 3: combine 8 partials, per-row log prob, deterministic mean.
// ---------------------------------------------------------------------------
__global__ void final_kernel(float* __restrict__ out) {
    __shared__ float red[1024];
    int t = threadIdx.x;
    float acc = 0.f;
    for (int r = t; r < NR; r += 1024) {
        float pos = 0.f, neg = 0.f, cnt = 0.f;
        #pragma unroll
        for (int p = 0; p < 8; p++) {
            pos += g_pos[p * NR + r];
            neg += g_neg[p * NR + r];
            cnt += g_cnt[p * NR + r];
        }
        acc += logf(pos / (pos + neg)) / cnt;
    }
    red[t] = acc;
    __syncthreads();
    for (int s = 512; s > 0; s >>= 1) {
        if (t < s) red[t] += red[t + s];
        __syncthreads();
    }
    if (t == 0) out[0] = -red[0] / (float)NR;
}

// ---------------------------------------------------------------------------
extern "C" void kernel_launch(void* const* d_in, const int* in_sizes, int n_in,
                              void* d_out, int out_size) {
    const float* features = (const float*)d_in[0];
    const int*   pmask    = (const int*)d_in[1];
    const int*   nmask    = (const int*)d_in[2];
    float* out = (float*)d_out;

    cudaFuncSetAttribute(hmma_main,
                         cudaFuncAttributeMaxDynamicSharedMemorySize, SMEM_TOTAL);

    prepack_kernel<<<NR / 8, NT>>>(features);
    dim3 grid(NR / TI, JSPLIT);
    hmma_main<<<grid, NT, SMEM_TOTAL>>>(pmask, nmask);
    final_kernel<<<1, 1024>>>(out);
}

// round 5
// speedup vs baseline: 3.2137x; 1.0857x over previous
#include <cuda_runtime.h>
#include <cuda_fp16.h>
#include <cstdint>
#include <math.h>

#define NR 8192
#define DDIM 128
#define EXPK ((1.0f/0.07f)*1.44269504f)   /* INV_T * log2(e) */
#define JSPLIT 2
#define JRANGE (NR/JSPLIT)      /* 4096 */
#define TI 64
#define TJ 128
#define NSTEP (JRANGE/TJ)       /* 32 */
#define NT 256

#define SM_AHI 0
#define SM_B0  16384
#define SM_B1  49152
#define SMEM_TOTAL 81920        /* 80 KB -> 2 CTAs/SM */

// Static device scratch (no allocations allowed).
__device__ __half g_hi[(size_t)NR * DDIM];
__device__ float g_pos[8 * NR];
__device__ float g_neg[8 * NR];
__device__ float g_cnt[8 * NR];

// ---------------------------------------------------------------------------
__device__ __forceinline__ uint32_t smem_u32(const void* p) {
    uint32_t a;
    asm("{ .reg .u64 t; cvta.to.shared.u64 t, %1; cvt.u32.u64 %0, t; }"
        : "=r"(a) : "l"(p));
    return a;
}
__device__ __forceinline__ void cp16(uint32_t dst, const void* src) {
    asm volatile("cp.async.cg.shared.global [%0], [%1], 16;"
                 :: "r"(dst), "l"(src));
}
#define CP_COMMIT() asm volatile("cp.async.commit_group;" ::: "memory")
#define CP_WAIT0()  asm volatile("cp.async.wait_group 0;" ::: "memory")

__device__ __forceinline__ void ldmx4(uint32_t addr, uint32_t& r0, uint32_t& r1,
                                      uint32_t& r2, uint32_t& r3) {
    asm volatile("ldmatrix.sync.aligned.m8n8.x4.shared.b16 {%0,%1,%2,%3}, [%4];"
                 : "=r"(r0), "=r"(r1), "=r"(r2), "=r"(r3) : "r"(addr));
}
__device__ __forceinline__ void mma16816(float* c, const uint32_t* a,
                                         uint32_t b0, uint32_t b1) {
    asm volatile(
        "mma.sync.aligned.m16n8k16.row.col.f32.f16.f16.f32 "
        "{%0,%1,%2,%3},{%4,%5,%6,%7},{%8,%9},{%0,%1,%2,%3};"
        : "+f"(c[0]), "+f"(c[1]), "+f"(c[2]), "+f"(c[3])
        : "r"(a[0]), "r"(a[1]), "r"(a[2]), "r"(a[3]), "r"(b0), "r"(b1));
}
__device__ __forceinline__ uint32_t swz(int row, int c) {
    return (uint32_t)(row * 256 + ((c ^ (row & 7)) << 4));
}
__device__ __forceinline__ float mask2f(int m) {
    return __int_as_float(m * 0x3f800000);   // m in {0,1}
}

// ---------------------------------------------------------------------------
// Kernel 1: normalize rows, fp32 -> fp16. Warp per row.
// ---------------------------------------------------------------------------
__global__ void prepack_kernel(const float* __restrict__ f) {
    int row = blockIdx.x * 8 + (threadIdx.x >> 5);
    int l = threadIdx.x & 31;
    float4 v = *(const float4*)(f + (size_t)row * DDIM + l * 4);
    float sq = fmaf(v.x, v.x, fmaf(v.y, v.y, fmaf(v.z, v.z, v.w * v.w)));
    #pragma unroll
    for (int o = 16; o > 0; o >>= 1) sq += __shfl_xor_sync(0xffffffffu, sq, o);
    float inv = 1.0f / fmaxf(sqrtf(sq), 1e-8f);
    __half2 a = __floats2half2_rn(v.x * inv, v.y * inv);
    __half2 b = __floats2half2_rn(v.z * inv, v.w * inv);
    uint2 uh;
    uh.x = *(uint32_t*)&a; uh.y = *(uint32_t*)&b;
    *(uint2*)(g_hi + (size_t)row * DDIM + l * 4) = uh;
}

// ---------------------------------------------------------------------------
template<int ROWS>
__device__ __forceinline__ void fill_tile(uint32_t sdst, const __half* gsrc, int tid) {
    #pragma unroll
    for (int r = 0; r < ROWS * 16 / NT; r++) {
        int idx = tid + r * NT;
        int row = idx >> 4, c = idx & 15;
        cp16(sdst + swz(row, c),
             (const char*)(gsrc + (size_t)row * DDIM) + c * 16);
    }
}

// ---------------------------------------------------------------------------
// Kernel 2: HMMA GEMM (fp16 hi) + fused exp/mask/row-sum epilogue,
// with register-pipelined mask loads.
// Grid (128 i-tiles, 2 j-splits). 256 threads, warps 2x4, warp tile 32x32.
// ---------------------------------------------------------------------------
extern __shared__ char dsm[];

__global__ __launch_bounds__(NT, 2) void hmma_main(
    const int* __restrict__ pmask, const int* __restrict__ nmask) {
    const uint32_t sb = smem_u32(dsm);
    const int tid = threadIdx.x, lid = tid & 31, wid = tid >> 5;
    const int wm = wid >> 2, wn = wid & 3;
    const int i0 = blockIdx.x * TI;
    const int split = blockIdx.y;
    const int jbase = split * JRANGE;

    fill_tile<TI>(sb + SM_AHI, g_hi + (size_t)i0 * DDIM, tid);
    fill_tile<TJ>(sb + SM_B0,  g_hi + (size_t)jbase * DDIM, tid);
    CP_COMMIT();
    CP_WAIT0();
    __syncthreads();

    float pos[4] = {0, 0, 0, 0}, neg[4] = {0, 0, 0, 0};
    int cnt[4] = {0, 0, 0, 0};

    const int arow0 = wm * 32 + (lid & 15);
    const int asel  = lid >> 4;
    const int brow0 = wn * 32 + (lid & 7) + ((lid & 16) ? 8 : 0);
    const int bsel  = (lid >> 3) & 1;
    const int idiag = (i0 & ~127);
    const int jcol = wn * 32 + (lid & 3) * 2;          // j offset within tile
    // per-(mt,hf) global row
    int igr[2][2];
    const int* pmr[2][2];
    const int* nmr[2][2];
    #pragma unroll
    for (int mt = 0; mt < 2; mt++)
        #pragma unroll
        for (int hf = 0; hf < 2; hf++) {
            int ig = i0 + wm * 32 + mt * 16 + hf * 8 + (lid >> 2);
            igr[mt][hf] = ig;
            pmr[mt][hf] = pmask + (size_t)ig * NR;
            nmr[mt][hf] = nmask + (size_t)ig * NR;
        }

    for (int t = 0; t < NSTEP; t++) {
        const int buf = t & 1;
        const uint32_t Bbase = sb + (buf ? SM_B1 : SM_B0);
        const int j0 = jbase + t * TJ;
        if (t + 1 < NSTEP) {
            fill_tile<TJ>(sb + (buf ? SM_B0 : SM_B1),
                          g_hi + (size_t)(j0 + TJ) * DDIM, tid);
            CP_COMMIT();
        }
        // L2-prefetch this step's mask block
        {
            const char* pp = (const char*)(pmask + (size_t)(i0 + (tid >> 2)) * NR + j0)
                             + (tid & 3) * 128;
            const char* np = (const char*)(nmask + (size_t)(i0 + (tid >> 2)) * NR + j0)
                             + (tid & 3) * 128;
            asm volatile("prefetch.global.L2 [%0];" :: "l"(pp));
            asm volatile("prefetch.global.L2 [%0];" :: "l"(np));
        }

        // Preload mt=0 masks into registers (latency hides under MMA phase).
        int2 pv0[2][4], nv0[2][4];
        #pragma unroll
        for (int hf = 0; hf < 2; hf++)
            #pragma unroll
            for (int nt = 0; nt < 4; nt++) {
                int j = j0 + jcol + nt * 8;
                pv0[hf][nt] = *(const int2*)(pmr[0][hf] + j);
                nv0[hf][nt] = *(const int2*)(nmr[0][hf] + j);
            }

        float acc[2][4][4];
        #pragma unroll
        for (int mt = 0; mt < 2; mt++)
            #pragma unroll
            for (int nt = 0; nt < 4; nt++)
                #pragma unroll
                for (int q = 0; q < 4; q++) acc[mt][nt][q] = 0.f;

        #pragma unroll
        for (int kk = 0; kk < 8; kk++) {
            uint32_t b[2][4];
            #pragma unroll
            for (int np = 0; np < 2; np++)
                ldmx4(Bbase + swz(brow0 + np * 16, 2 * kk + bsel),
                      b[np][0], b[np][1], b[np][2], b[np][3]);
            uint32_t a[2][4];
            #pragma unroll
            for (int mt = 0; mt < 2; mt++)
                ldmx4(sb + SM_AHI + swz(arow0 + mt * 16, 2 * kk + asel),
                      a[mt][0], a[mt][1], a[mt][2], a[mt][3]);
            #pragma unroll
            for (int np = 0; np < 2; np++)
                #pragma unroll
                for (int mt = 0; mt < 2; mt++) {
                    mma16816(acc[mt][2 * np],     a[mt], b[np][0], b[np][1]);
                    mma16816(acc[mt][2 * np + 1], a[mt], b[np][2], b[np][3]);
                }
        }

        // Issue mt=1 mask loads before consuming mt=0 (hide L2 latency).
        int2 pv1[2][4], nv1[2][4];
        #pragma unroll
        for (int hf = 0; hf < 2; hf++)
            #pragma unroll
            for (int nt = 0; nt < 4; nt++) {
                int j = j0 + jcol + nt * 8;
                pv1[hf][nt] = *(const int2*)(pmr[1][hf] + j);
                nv1[hf][nt] = *(const int2*)(nmr[1][hf] + j);
            }

        const bool diag = (j0 == idiag);
        #pragma unroll
        for (int mt = 0; mt < 2; mt++) {
            #pragma unroll
            for (int hf = 0; hf < 2; hf++) {
                const int rr = mt * 2 + hf;
                const int ig = igr[mt][hf];
                float p = pos[rr], n = neg[rr];
                int c = cnt[rr];
                #pragma unroll
                for (int nt = 0; nt < 4; nt++) {
                    const int j = j0 + jcol + nt * 8;
                    int2 pv = mt ? pv1[hf][nt] : pv0[hf][nt];
                    int2 nv = mt ? nv1[hf][nt] : nv0[hf][nt];
                    if (diag) {
                        if (j == ig)     { pv.x = 0; nv.x = 0; }
                        if (j + 1 == ig) { pv.y = 0; nv.y = 0; }
                    }
                    float e0 = exp2f(acc[mt][nt][hf * 2 + 0] * EXPK);
                    float e1 = exp2f(acc[mt][nt][hf * 2 + 1] * EXPK);
                    p = fmaf(e0, mask2f(pv.x), p);
                    p = fmaf(e1, mask2f(pv.y), p);
                    n = fmaf(e0, mask2f(nv.x), n);
                    n = fmaf(e1, mask2f(nv.y), n);
                    c += pv.x + pv.y;
                }
                pos[rr] = p; neg[rr] = n; cnt[rr] = c;
            }
        }

        if (t + 1 < NSTEP) CP_WAIT0();
        __syncthreads();
    }

    // quad-lane reduce + store
    #pragma unroll
    for (int rr = 0; rr < 4; rr++) {
        float p = pos[rr], n = neg[rr], c = (float)cnt[rr];
        p += __shfl_xor_sync(0xffffffffu, p, 1);
        p += __shfl_xor_sync(0xffffffffu, p, 2);
        n += __shfl_xor_sync(0xffffffffu, n, 1);
        n += __shfl_xor_sync(0xffffffffu, n, 2);
        c += __shfl_xor_sync(0xffffffffu, c, 1);
        c += __shfl_xor_sync(0xffffffffu, c, 2);
        if ((lid & 3) == 0) {
            int mt = rr >> 1, hf = rr & 1;
            int ig = igr[mt][hf];
            int part = split * 4 + wn;
            g_pos[part * NR + ig] = p;
            g_neg[part * NR + ig] = n;
            g_cnt[part * NR + ig] = c;
        }
    }
}

// ---------------------------------------------------------------------------
// Kernel 3: combine 8 partials, per-row log prob, deterministic mean.
// ---------------------------------------------------------------------------
__global__ void final_kernel(float* __restrict__ out) {
    __shared__ float red[1024];
    int t = threadIdx.x;
    float acc = 0.f;
    for (int r = t; r < NR; r += 1024) {
        float pos = 0.f, neg = 0.f, cnt = 0.f;
        #pragma unroll
        for (int p = 0; p < 8; p++) {
            pos += g_pos[p * NR + r];
            neg += g_neg[p * NR + r];
            cnt += g_cnt[p * NR + r];
        }
        acc += logf(pos / (pos + neg)) / cnt;
    }
    red[t] = acc;
    __syncthreads();
    for (int s = 512; s > 0; s >>= 1) {
        if (t < s) red[t] += red[t + s];
        __syncthreads();
    }
    if (t == 0) out[0] = -red[0] / (float)NR;
}

// ---------------------------------------------------------------------------
extern "C" void kernel_launch(void* const* d_in, const int* in_sizes, int n_in,
                              void* d_out, int out_size) {
    const float* features = (const float*)d_in[0];
    const int*   pmask    = (const int*)d_in[1];
    const int*   nmask    = (const int*)d_in[2];
    float* out = (float*)d_out;

    cudaFuncSetAttribute(hmma_main,
                         cudaFuncAttributeMaxDynamicSharedMemorySize, SMEM_TOTAL);

    prepack_kernel<<<NR / 8, NT>>>(features);
    dim3 grid(NR / TI, JSPLIT);
    hmma_main<<<grid, NT, SMEM_TOTAL>>>(pmask, nmask);
    final_kernel<<<1, 1024>>>(out);
}